// round 5
// baseline (speedup 1.0000x reference)
#include <cuda_runtime.h>
#include <cstdint>

#define SEQ_LEN   2048
#define STATE_LEN 1024
#define N_POI     10000
#define ROW_BYTES (N_POI * 4)            // 40000, multiple of 16
#define EPS_VAL   1e-6f
#define THREADS   256
#define PER_T     (SEQ_LEN / THREADS)    // 8
#define GRID      (STATE_LEN / 2)        // 512: 2 rows per CTA
#define SMEM_DYN  (2 * ROW_BYTES)        // 80000 B double buffer

extern __shared__ float sbuf[];          // [2][N_POI]

__device__ __forceinline__ void mbar_wait(uint32_t addr, uint32_t parity)
{
    uint32_t done;
    asm volatile(
        "{\n\t"
        ".reg .pred p;\n\t"
        "mbarrier.try_wait.parity.acquire.cta.shared::cta.b64 p, [%1], %2;\n\t"
        "selp.b32 %0, 1, 0, p;\n\t"
        "}"
        : "=r"(done) : "r"(addr), "r"(parity) : "memory");
    if (!done) {
        asm volatile(
            "{\n\t"
            ".reg .pred P1;\n\t"
            "W_%=:\n\t"
            "mbarrier.try_wait.parity.acquire.cta.shared::cta.b64 P1, [%0], %1, 0x989680;\n\t"
            "@P1 bra.uni D_%=;\n\t"
            "bra.uni W_%=;\n\t"
            "D_%=:\n\t"
            "}"
            :: "r"(addr), "r"(parity) : "memory");
    }
}

__global__ __launch_bounds__(THREADS)
void attn_loc_kernel(const int* __restrict__ his,
                     const int* __restrict__ cur,
                     const float* __restrict__ mat,
                     float* __restrict__ out)
{
    __shared__ float sred[THREADS / 32];
    __shared__ alignas(8) uint64_t mbar[2];

    const int tid = threadIdx.x;
    const uint32_t mb0 = (uint32_t)__cvta_generic_to_shared(&mbar[0]);
    const uint32_t mb1 = (uint32_t)__cvta_generic_to_shared(&mbar[1]);

    if (tid == 0) {
        asm volatile("mbarrier.init.shared.b64 [%0], %1;" :: "r"(mb0), "r"(1) : "memory");
        asm volatile("mbarrier.init.shared.b64 [%0], %1;" :: "r"(mb1), "r"(1) : "memory");
    }
    __syncthreads();

    const int row0 = blockIdx.x;
    const int row1 = blockIdx.x + GRID;

    // Kick off BOTH row copies immediately: 80KB in flight per CTA.
    if (tid == 0) {
        const uint32_t dst0 = (uint32_t)__cvta_generic_to_shared(sbuf);
        const uint32_t dst1 = dst0 + ROW_BYTES;
        const char* src0 = (const char*)mat + (size_t)__ldg(cur + row0) * ROW_BYTES;
        const char* src1 = (const char*)mat + (size_t)__ldg(cur + row1) * ROW_BYTES;
        asm volatile("mbarrier.arrive.expect_tx.shared.b64 _, [%0], %1;"
                     :: "r"(mb0), "r"((uint32_t)ROW_BYTES) : "memory");
        asm volatile(
            "cp.async.bulk.shared::cluster.global.mbarrier::complete_tx::bytes "
            "[%0], [%1], %2, [%3];"
            :: "r"(dst0), "l"(src0), "r"((uint32_t)ROW_BYTES), "r"(mb0) : "memory");
        asm volatile("mbarrier.arrive.expect_tx.shared.b64 _, [%0], %1;"
                     :: "r"(mb1), "r"((uint32_t)ROW_BYTES) : "memory");
        asm volatile(
            "cp.async.bulk.shared::cluster.global.mbarrier::complete_tx::bytes "
            "[%0], [%1], %2, [%3];"
            :: "r"(dst1), "l"(src1), "r"((uint32_t)ROW_BYTES), "r"(mb1) : "memory");
    }

    // Index prefetch overlaps the TMAs (his is tiny and L2-resident).
    int cidx[PER_T];
#pragma unroll
    for (int k = 0; k < PER_T; k++)
        cidx[k] = __ldg(his + tid + k * THREADS);

#pragma unroll
    for (int half = 0; half < 2; half++) {
        const float* __restrict__ srow = sbuf + half * N_POI;
        mbar_wait(half ? mb1 : mb0, 0u);

        // Phase 1: gather from smem, map to energies, local max
        float v[PER_T];
        float mx = -INFINITY;
#pragma unroll
        for (int k = 0; k < PER_T; k++) {
            const float d = srow[cidx[k]];
            const float e = (d != 0.0f) ? (1.0f / d) : EPS_VAL;
            v[k] = e;
            mx = fmaxf(mx, e);
        }

        // Block max reduction
#pragma unroll
        for (int o = 16; o; o >>= 1)
            mx = fmaxf(mx, __shfl_xor_sync(0xffffffffu, mx, o));
        if ((tid & 31) == 0) sred[tid >> 5] = mx;
        __syncthreads();
        float bmax = sred[0];
#pragma unroll
        for (int w = 1; w < THREADS / 32; w++) bmax = fmaxf(bmax, sred[w]);
        __syncthreads();

        // Phase 2: exp + local sum
        float sum = 0.0f;
#pragma unroll
        for (int k = 0; k < PER_T; k++) {
            const float e = __expf(v[k] - bmax);
            v[k] = e;
            sum += e;
        }

        // Block sum reduction
#pragma unroll
        for (int o = 16; o; o >>= 1)
            sum += __shfl_xor_sync(0xffffffffu, sum, o);
        if ((tid & 31) == 0) sred[tid >> 5] = sum;
        __syncthreads();
        float bsum = 0.0f;
#pragma unroll
        for (int w = 0; w < THREADS / 32; w++) bsum += sred[w];
        __syncthreads();   // sred reused next half

        // Phase 3: normalize + coalesced store
        const float inv = 1.0f / bsum;
        const int row = half ? row1 : row0;
        float* __restrict__ orow = out + (size_t)row * SEQ_LEN;
#pragma unroll
        for (int k = 0; k < PER_T; k++)
            orow[tid + k * THREADS] = v[k] * inv;
    }
}

extern "C" void kernel_launch(void* const* d_in, const int* in_sizes, int n_in,
                              void* d_out, int out_size)
{
    const int*   his = (const int*)d_in[0];
    const int*   cur = (const int*)d_in[1];
    const float* mat = (const float*)d_in[2];
    float*       out = (float*)d_out;

    cudaFuncSetAttribute(attn_loc_kernel,
                         cudaFuncAttributeMaxDynamicSharedMemorySize, SMEM_DYN);
    attn_loc_kernel<<<GRID, THREADS, SMEM_DYN>>>(his, cur, mat, out);
}

// round 6
// speedup vs baseline: 1.1910x; 1.1910x over previous
#include <cuda_runtime.h>
#include <cstdint>

#define SEQ_LEN    2048
#define STATE_LEN  1024
#define N_POI      10000
#define ROW_BYTES  (N_POI * 4)           // 40000
#define HALF_ELEMS 5000
#define HALF_BYTES (HALF_ELEMS * 4)      // 20000, 16B-aligned
#define EPS_VAL    1e-6f
#define THREADS    256
#define PER_T      (SEQ_LEN / THREADS)   // 8

__device__ __forceinline__ void mbar_wait(uint32_t addr, uint32_t parity)
{
    uint32_t done;
    asm volatile(
        "{\n\t"
        ".reg .pred p;\n\t"
        "mbarrier.try_wait.parity.acquire.cta.shared::cta.b64 p, [%1], %2;\n\t"
        "selp.b32 %0, 1, 0, p;\n\t"
        "}"
        : "=r"(done) : "r"(addr), "r"(parity) : "memory");
    if (!done) {
        asm volatile(
            "{\n\t"
            ".reg .pred P1;\n\t"
            "W_%=:\n\t"
            "mbarrier.try_wait.parity.acquire.cta.shared::cta.b64 P1, [%0], %1, 0x989680;\n\t"
            "@P1 bra.uni D_%=;\n\t"
            "bra.uni W_%=;\n\t"
            "D_%=:\n\t"
            "}"
            :: "r"(addr), "r"(parity) : "memory");
    }
}

__global__ __launch_bounds__(THREADS)
void attn_loc_kernel(const int* __restrict__ his,
                     const int* __restrict__ cur,
                     const float* __restrict__ mat,
                     float* __restrict__ out)
{
    __shared__ alignas(128) float srow[N_POI];   // 40000 B row buffer
    __shared__ float sred[THREADS / 32];
    __shared__ alignas(8) uint64_t mbar[2];

    const int row = blockIdx.x;
    const int tid = threadIdx.x;
    const uint32_t mb0 = (uint32_t)__cvta_generic_to_shared(&mbar[0]);
    const uint32_t mb1 = (uint32_t)__cvta_generic_to_shared(&mbar[1]);

    if (tid == 0) {
        asm volatile("mbarrier.init.shared.b64 [%0], %1;" :: "r"(mb0), "r"(1) : "memory");
        asm volatile("mbarrier.init.shared.b64 [%0], %1;" :: "r"(mb1), "r"(1) : "memory");
    }
    __syncthreads();

    // Two-chunk TMA: gather on the first 20KB starts while the second streams.
    if (tid == 0) {
        const uint32_t dst = (uint32_t)__cvta_generic_to_shared(srow);
        const char* src = (const char*)mat + (size_t)__ldg(cur + row) * ROW_BYTES;
        asm volatile("mbarrier.arrive.expect_tx.shared.b64 _, [%0], %1;"
                     :: "r"(mb0), "r"((uint32_t)HALF_BYTES) : "memory");
        asm volatile(
            "cp.async.bulk.shared::cluster.global.mbarrier::complete_tx::bytes "
            "[%0], [%1], %2, [%3];"
            :: "r"(dst), "l"(src), "r"((uint32_t)HALF_BYTES), "r"(mb0) : "memory");
        asm volatile("mbarrier.arrive.expect_tx.shared.b64 _, [%0], %1;"
                     :: "r"(mb1), "r"((uint32_t)(ROW_BYTES - HALF_BYTES)) : "memory");
        asm volatile(
            "cp.async.bulk.shared::cluster.global.mbarrier::complete_tx::bytes "
            "[%0], [%1], %2, [%3];"
            :: "r"(dst + HALF_BYTES), "l"(src + HALF_BYTES),
               "r"((uint32_t)(ROW_BYTES - HALF_BYTES)), "r"(mb1) : "memory");
    }

    // Index prefetch overlaps the TMAs (his is tiny, L2-resident).
    int cidx[PER_T];
#pragma unroll
    for (int k = 0; k < PER_T; k++)
        cidx[k] = __ldg(his + tid + k * THREADS);

    float v[PER_T];
    float mx = -INFINITY;

    // Phase A: gather indices in the first half as soon as chunk0 lands.
    mbar_wait(mb0, 0u);
#pragma unroll
    for (int k = 0; k < PER_T; k++) {
        if (cidx[k] < HALF_ELEMS) {
            const float d = srow[cidx[k]];
            const float e = (d != 0.0f) ? __fdividef(1.0f, d) : EPS_VAL;
            v[k] = e;
            mx = fmaxf(mx, e);
        }
    }

    // Phase B: remaining indices once chunk1 lands.
    mbar_wait(mb1, 0u);
#pragma unroll
    for (int k = 0; k < PER_T; k++) {
        if (cidx[k] >= HALF_ELEMS) {
            const float d = srow[cidx[k]];
            const float e = (d != 0.0f) ? __fdividef(1.0f, d) : EPS_VAL;
            v[k] = e;
            mx = fmaxf(mx, e);
        }
    }

    // Block max reduction
#pragma unroll
    for (int o = 16; o; o >>= 1)
        mx = fmaxf(mx, __shfl_xor_sync(0xffffffffu, mx, o));
    if ((tid & 31) == 0) sred[tid >> 5] = mx;
    __syncthreads();
    float bmax = sred[0];
#pragma unroll
    for (int w = 1; w < THREADS / 32; w++) bmax = fmaxf(bmax, sred[w]);
    __syncthreads();

    // exp + local sum
    float sum = 0.0f;
#pragma unroll
    for (int k = 0; k < PER_T; k++) {
        const float e = __expf(v[k] - bmax);
        v[k] = e;
        sum += e;
    }

    // Block sum reduction
#pragma unroll
    for (int o = 16; o; o >>= 1)
        sum += __shfl_xor_sync(0xffffffffu, sum, o);
    if ((tid & 31) == 0) sred[tid >> 5] = sum;
    __syncthreads();
    float bsum = 0.0f;
#pragma unroll
    for (int w = 0; w < THREADS / 32; w++) bsum += sred[w];

    // normalize + coalesced store
    const float inv = __fdividef(1.0f, bsum);
    float* __restrict__ orow = out + (size_t)row * SEQ_LEN;
#pragma unroll
    for (int k = 0; k < PER_T; k++)
        orow[tid + k * THREADS] = v[k] * inv;
}

extern "C" void kernel_launch(void* const* d_in, const int* in_sizes, int n_in,
                              void* d_out, int out_size)
{
    const int*   his = (const int*)d_in[0];
    const int*   cur = (const int*)d_in[1];
    const float* mat = (const float*)d_in[2];
    float*       out = (float*)d_out;

    attn_loc_kernel<<<STATE_LEN, THREADS>>>(his, cur, mat, out);
}